// round 11
// baseline (speedup 1.0000x reference)
#include <cuda_runtime.h>
#include <stdint.h>

// Geometry fixed by the problem: outputs/masks are [2,1,64,256,256]
#define HH 256
#define WW 256
#define BATCH 2
#define SLICES 128
#define WPR 8                       // 32-bit words per 256-px row
#define NWORDS (HH * WPR)           // 2048 words per slice
#define NPIX (HH * WW)              // 65536 px per slice
#define NCTA2 256                   // main kernel: 2 CTAs per slice
#define HALF_PX 32768               // px per half-slice
#define WIN_ROWS 192                // 128 own rows + 32 halo each side
#define WIN_WORDS (WIN_ROWS * WPR)  // 1536
#define OWN_W0 256                  // window word index of first own word
#define OWN_WORDS 1024              // own words per CTA

__device__ uint32_t g_mb[SLICES * NWORDS];      // packed mask bits (1 MB)
__device__ uint32_t g_pl[5][NCTA2][OWN_WORDS];  // rare slow-path plane spill
__device__ double   g_cta[NCTA2][3];            // per-CTA partials
__device__ unsigned g_ticket = 0;

// ================= K1: pack masks -> bits (MLP-batched streaming) ============
__global__ __launch_bounds__(256)
void pack_kernel(const int* __restrict__ mskp) {
    const int tid = threadIdx.x;
    const int lane = tid & 31;
    const int4* mp4 = reinterpret_cast<const int4*>(mskp);
    const size_t gbase = (size_t)blockIdx.x * 2048;   // int4 groups per CTA

#pragma unroll
    for (int h = 0; h < 2; h++) {
        int4 va[4];
#pragma unroll
        for (int j = 0; j < 4; j++)                   // 4 back-to-back LDG.128
            va[j] = mp4[gbase + (size_t)(h * 4 + j) * 256 + tid];
#pragma unroll
        for (int j = 0; j < 4; j++) {
            int4 v = va[j];
            unsigned nib = (v.x ? 1u : 0u) | (v.y ? 2u : 0u)
                         | (v.z ? 4u : 0u) | (v.w ? 8u : 0u);
            unsigned w = nib << ((lane & 7) * 4);
            w |= __shfl_xor_sync(0xffffffffu, w, 1);
            w |= __shfl_xor_sync(0xffffffffu, w, 2);
            w |= __shfl_xor_sync(0xffffffffu, w, 4);
            size_t g = gbase + (size_t)(h * 4 + j) * 256 + tid;
            if ((lane & 7) == 0) g_mb[g >> 3] = w;
        }
    }
}

// ================= K2: halo cascade + decode + finalize =======================
__global__ __launch_bounds__(512, 2)
void main_kernel(const float* __restrict__ outp, float* __restrict__ out) {
    __shared__ uint32_t wm[WIN_WORDS];        // window mask bits     (6 KB)
    __shared__ uint32_t buf[2][WIN_WORDS];    // cascade double buf  (12 KB)
    __shared__ uint32_t ebw[WIN_WORDS];       // window edge bits     (6 KB)
    __shared__ int      base_s[OWN_WORDS];    // per-own-word LUT base(4 KB)
    __shared__ uint32_t hm_s[OWN_WORDS];      // per-own-word hi mask (4 KB)
    __shared__ float lut[64];
    __shared__ double red0[16], red1[16], red2[16];
    __shared__ int s_last;

    const int cta = blockIdx.x;
    const int slice = cta >> 1;
    const int half = cta & 1;
    const int tid = threadIdx.x;
    const int lane = tid & 31;
    const int wid = tid >> 5;
    const int arow = half * 128;              // first own row in slice

    // weight LUT: acc 0..21; dist=(22-acc)/22; w=2/(1+exp(10*dist)); padded
    if (tid < 64) {
        int a = tid < 22 ? tid : 21;
        float dist = (22.0f - (float)a) / 22.0f;
        lut[tid] = 2.0f / (1.0f + expf(10.0f * dist));
    }

    // ---- load 192-row bitmask window (L2-resident, written by K1) ----
#pragma unroll
    for (int k = 0; k < 3; k++) {
        int ww = k * 512 + tid;               // window word index
        int grow = arow - 32 + (ww >> 3);     // global row in slice
        uint32_t v = 0u;
        if (grow >= 0 && grow < HH)
            v = g_mb[slice * NWORDS + grow * WPR + (ww & 7)];
        wm[ww] = v;
    }
    __syncthreads();

    // ---- edge on window (zero-pad; wrongness stays >20 rows from own rows) ----
    uint32_t P0[3], P1[3], P2[3], P3[3], P4[3];   // coverage K, bit-sliced
#pragma unroll
    for (int k = 0; k < 3; k++) {
        int ww = k * 512 + tid;
        int rw = ww >> 3, c = ww & 7;
        uint32_t m  = wm[ww];
        uint32_t up = rw              ? wm[ww - WPR] : 0u;
        uint32_t dn = (rw < WIN_ROWS - 1) ? wm[ww + WPR] : 0u;
        uint32_t pv = c               ? wm[ww - 1]   : 0u;
        uint32_t nx = (c < WPR - 1)   ? wm[ww + 1]   : 0u;
        uint32_t lf = (m << 1) | (pv >> 31);
        uint32_t rt = (m >> 1) | (nx << 31);
        uint32_t e = m & ~(up & dn & lf & rt);
        buf[0][ww] = e;
        ebw[ww] = e;
        P0[k] = 0u; P1[k] = 0u; P2[k] = 0u; P3[k] = 0u; P4[k] = 0u;
    }
    __syncthreads();

    // ---- cascaded 3x3 OR-dilations with saturation early-exit ----
    int extra = 0;
    int sb = 0;
    for (int r = 1; r <= 20; r++) {
        const uint32_t* src = buf[sb];
        uint32_t* dst = buf[sb ^ 1];
        uint32_t allw = 0xffffffffu;
#pragma unroll
        for (int k = 0; k < 3; k++) {
            int ww = k * 512 + tid;
            int rw = ww >> 3, c = ww & 7;
            // vertical OR for words ww-1, ww, ww+1
            uint32_t vc = src[ww];
            if (rw)                vc |= src[ww - WPR];
            if (rw < WIN_ROWS - 1) vc |= src[ww + WPR];
            uint32_t vl = 0u, vr = 0u;
            if (c) {
                vl = src[ww - 1];
                if (rw)                vl |= src[ww - 1 - WPR];
                if (rw < WIN_ROWS - 1) vl |= src[ww - 1 + WPR];
            }
            if (c < WPR - 1) {
                vr = src[ww + 1];
                if (rw)                vr |= src[ww + 1 - WPR];
                if (rw < WIN_ROWS - 1) vr |= src[ww + 1 + WPR];
            }
            uint32_t nw = vc | (vc << 1) | (vl >> 31) | (vc >> 1) | (vr << 31);
            dst[ww] = nw;
            allw &= nw;
            uint32_t cy = nw, t;              // ripple-carry +1 where covered
            t = P0[k] & cy; P0[k] ^= cy; cy = t;
            t = P1[k] & cy; P1[k] ^= cy; cy = t;
            t = P2[k] & cy; P2[k] ^= cy; cy = t;
            t = P3[k] & cy; P3[k] ^= cy; cy = t;
            P4[k] ^= cy;
        }
        sb ^= 1;
        if (__syncthreads_and(allw == 0xffffffffu)) { extra = 20 - r; break; }
    }

    // ---- per-own-word decode metadata: acc = K + edge, K in {kt-1, kt} ----
#pragma unroll
    for (int k = 0; k < 3; k++) {
        int ww = k * 512 + tid;
        if (ww >= OWN_W0 && ww < OWN_W0 + OWN_WORDS) {
            int lw = ww - OWN_W0;
            uint32_t p0 = P0[k], p1 = P1[k], p2 = P2[k], p3 = P3[k], p4 = P4[k];
            unsigned kt = ((p0 >> 31) & 1u) | (((p1 >> 31) & 1u) << 1)
                        | (((p2 >> 31) & 1u) << 2) | (((p3 >> 31) & 1u) << 3)
                        | (((p4 >> 31) & 1u) << 4);
            uint32_t mhi = ((kt & 1u)  ? p0 : ~p0) & ((kt & 2u)  ? p1 : ~p1)
                         & ((kt & 4u)  ? p2 : ~p2) & ((kt & 8u)  ? p3 : ~p3)
                         & ((kt & 16u) ? p4 : ~p4);
            uint32_t mlo = 0u;
            if (kt) {
                unsigned kl = kt - 1u;
                mlo = ((kl & 1u)  ? p0 : ~p0) & ((kl & 2u)  ? p1 : ~p1)
                    & ((kl & 4u)  ? p2 : ~p2) & ((kl & 8u)  ? p3 : ~p3)
                    & ((kl & 16u) ? p4 : ~p4);
            }
            bool valid = (mhi | mlo) == 0xffffffffu;
            base_s[lw] = valid ? ((int)kt - 1 + extra) : -100;
            hm_s[lw] = mhi;
            if (!valid) {                     // rare: spill planes to gmem
                g_pl[0][cta][lw] = p0;
                g_pl[1][cta][lw] = p1;
                g_pl[2][cta][lw] = p2;
                g_pl[3][cta][lw] = p3;
                g_pl[4][cta][lw] = p4;
            }
        }
    }
    __syncthreads();

    // ---- decode own half: 16 float4/thread in 4 MLP-batched groups ----
    const float4* op4 = reinterpret_cast<const float4*>(outp)
                      + (size_t)slice * (NPIX / 4) + (size_t)half * (HALF_PX / 4);
    float s_ia = 0.f, s_in = 0.f, s_ta = 0.f;
#pragma unroll
    for (int bt = 0; bt < 4; bt++) {
        float4 va[4];
#pragma unroll
        for (int j = 0; j < 4; j++)           // 4 back-to-back LDG.128
            va[j] = op4[(bt * 4 + j) * 512 + tid];
#pragma unroll
        for (int j = 0; j < 4; j++) {
            int g = (bt * 4 + j) * 512 + tid;
            int lw = g >> 3;
            int i0 = (g & 7) * 4;
            int wbase = base_s[lw];
            uint32_t qm = wm[lw + OWN_W0] >> i0;
            uint32_t qe = ebw[lw + OWN_W0] >> i0;
            float vv[4] = {va[j].x, va[j].y, va[j].z, va[j].w};
            if (wbase != -100) {
                uint32_t qh = hm_s[lw] >> i0;
#pragma unroll
                for (int e = 0; e < 4; e++) {
                    int idx = wbase + (int)((qh >> e) & 1u) + (int)((qe >> e) & 1u);
                    float w = lut[idx];
                    float f = vv[e] * w;
                    s_ia += f;
                    if ((qm >> e) & 1u) { s_in += f; s_ta += w; }
                }
            } else {
                uint32_t q0 = g_pl[0][cta][lw] >> i0;
                uint32_t q1 = g_pl[1][cta][lw] >> i0;
                uint32_t q2 = g_pl[2][cta][lw] >> i0;
                uint32_t q3 = g_pl[3][cta][lw] >> i0;
                uint32_t q4 = g_pl[4][cta][lw] >> i0;
#pragma unroll
                for (int e = 0; e < 4; e++) {
                    unsigned a = ((q0 >> e) & 1u)
                               | (((q1 >> e) & 1u) << 1)
                               | (((q2 >> e) & 1u) << 2)
                               | (((q3 >> e) & 1u) << 3)
                               | (((q4 >> e) & 1u) << 4);
                    a += ((qe >> e) & 1u) + extra;
                    float w = lut[a];
                    float f = vv[e] * w;
                    s_ia += f;
                    if ((qm >> e) & 1u) { s_in += f; s_ta += w; }
                }
            }
        }
    }

    // ---- reduce to per-CTA partials ----
    double d0 = (double)s_in, d1 = (double)s_ia, d2 = (double)s_ta;
#pragma unroll
    for (int o = 16; o > 0; o >>= 1) {
        d0 += __shfl_down_sync(0xffffffffu, d0, o);
        d1 += __shfl_down_sync(0xffffffffu, d1, o);
        d2 += __shfl_down_sync(0xffffffffu, d2, o);
    }
    if (lane == 0) { red0[wid] = d0; red1[wid] = d1; red2[wid] = d2; }
    __syncthreads();
    if (wid == 0) {
        double a0 = (lane < 16) ? red0[lane] : 0.0;
        double a1 = (lane < 16) ? red1[lane] : 0.0;
        double a2 = (lane < 16) ? red2[lane] : 0.0;
#pragma unroll
        for (int o = 8; o > 0; o >>= 1) {
            a0 += __shfl_down_sync(0xffffffffu, a0, o);
            a1 += __shfl_down_sync(0xffffffffu, a1, o);
            a2 += __shfl_down_sync(0xffffffffu, a2, o);
        }
        if (lane == 0) {
            g_cta[cta][0] = a0;
            g_cta[cta][1] = a1;
            g_cta[cta][2] = a2;
        }
    }

    // ---- fused finalize: last-arriving CTA computes the scalar loss ----
    if (tid == 0) {
        __threadfence();
        unsigned t = atomicAdd(&g_ticket, 1u);
        s_last = (t == NCTA2 - 1);
    }
    __syncthreads();
    if (s_last) {
        __threadfence();
        // warps 0-3: batch 0 (ctas 0..127); warps 4-7: batch 1 (ctas 128..255)
        if (wid < 8) {
            int c = wid * 32 + lane;
            double i0 = g_cta[c][0];
            double a0 = g_cta[c][1];
            double t0 = g_cta[c][2];
#pragma unroll
            for (int o = 16; o > 0; o >>= 1) {
                i0 += __shfl_down_sync(0xffffffffu, i0, o);
                a0 += __shfl_down_sync(0xffffffffu, a0, o);
                t0 += __shfl_down_sync(0xffffffffu, t0, o);
            }
            if (lane == 0) { red0[wid] = i0; red1[wid] = a0; red2[wid] = t0; }
        }
        __syncthreads();
        if (tid == 0) {
            double loss = 0.0;
#pragma unroll
            for (int b = 0; b < BATCH; b++) {
                double I = 0.0, A = 0.0, T = 0.0;
#pragma unroll
                for (int q = 0; q < 4; q++) {
                    I += red0[b * 4 + q];
                    A += red1[b * 4 + q];
                    T += red2[b * 4 + q];
                }
                loss += (T == 0.0) ? 0.0 : (1.0 - 2.0 * I / (A + T + 2.0e-6));
            }
            out[0] = (float)(loss * 0.5);     // mean over BATCH=2
            g_ticket = 0;                     // reset for next graph replay
        }
    }
}

extern "C" void kernel_launch(void* const* d_in, const int* in_sizes, int n_in,
                              void* d_out, int out_size) {
    const float* outputs = (const float*)d_in[0];  // float32 [2,1,64,256,256]
    const int*   masks   = (const int*)d_in[1];    // int32   [2,1,64,256,256]
    float* out = (float*)d_out;

    pack_kernel<<<1024, 256>>>(masks);
    main_kernel<<<NCTA2, 512>>>(outputs, out);
}

// round 12
// speedup vs baseline: 1.0969x; 1.0969x over previous
#include <cuda_runtime.h>
#include <stdint.h>

// Geometry fixed by the problem: outputs/masks are [2,1,64,256,256]
#define HH 256
#define WW 256
#define BATCH 2
#define SLICES 128
#define WPR 8                        // 32-bit words per 256-px row
#define NWORDS (HH * WPR)            // 2048 words per slice
#define NPIX (HH * WW)               // 65536 px per slice
#define TOTW (SLICES * NWORDS)       // 262144 words total
#define NCTA 1024                    // pack/decode grid

__device__ uint32_t g_mb[TOTW];      // mask bits  (1 MB)
__device__ uint32_t g_eb[TOTW];      // edge bits  (1 MB)
__device__ int      g_bs[TOTW];      // per-word LUT base incl extra; -100 = slow (1 MB... int)
__device__ uint32_t g_hm[TOTW];      // per-word K==ktop bitmask (1 MB)
__device__ uint32_t g_pl[5][TOTW];   // rare slow-path planes
__device__ int      g_extra[SLICES];
__device__ double   g_cta[NCTA][3];
__device__ unsigned g_ticket = 0;

// ================= K1: pack masks -> bits (MLP=8 front-batched) ==============
__global__ __launch_bounds__(256)
void pack_kernel(const int* __restrict__ mskp) {
    const int tid = threadIdx.x;
    const int lane = tid & 31;
    const int4* mp4 = reinterpret_cast<const int4*>(mskp);
    const size_t gb = (size_t)blockIdx.x * 2048;    // int4 groups per CTA

    int4 va[8];
#pragma unroll
    for (int j = 0; j < 8; j++)                     // 8 back-to-back LDG.128
        va[j] = mp4[gb + (size_t)j * 256 + tid];
#pragma unroll
    for (int j = 0; j < 8; j++) {
        int4 v = va[j];
        unsigned nib = (v.x ? 1u : 0u) | (v.y ? 2u : 0u)
                     | (v.z ? 4u : 0u) | (v.w ? 8u : 0u);
        unsigned w = nib << ((lane & 7) * 4);
        w |= __shfl_xor_sync(0xffffffffu, w, 1);
        w |= __shfl_xor_sync(0xffffffffu, w, 2);
        w |= __shfl_xor_sync(0xffffffffu, w, 4);
        if ((lane & 7) == 0) g_mb[(gb + (size_t)j * 256 + tid) >> 3] = w;
    }
}

// ================= K2: per-slice cascade + per-word metadata ==================
__global__ __launch_bounds__(1024, 1)
void cascade_kernel() {
    __shared__ uint32_t mb[NWORDS];
    __shared__ uint32_t buf[2][NWORDS];

    const int slice = blockIdx.x;
    const int tid = threadIdx.x;

#pragma unroll
    for (int j = 0; j < 2; j++)
        mb[j * 1024 + tid] = g_mb[slice * NWORDS + j * 1024 + tid];
    __syncthreads();

    // thread owns a quarter-row: 2 consecutive words
    const int row = tid >> 2;
    const int cw0 = (tid & 3) * 2;
    const int wb = row * WPR + cw0;

    uint32_t P0[2], P1[2], P2[2], P3[2], P4[2];     // coverage K, bit-sliced

    // edge = m & ~(up & down & left & right), zero padded
#pragma unroll
    for (int j = 0; j < 2; j++) {
        int cw = cw0 + j, gw = wb + j;
        uint32_t m  = mb[gw];
        uint32_t up = row            ? mb[gw - WPR] : 0u;
        uint32_t dn = (row < HH - 1) ? mb[gw + WPR] : 0u;
        uint32_t pv = cw             ? mb[gw - 1]   : 0u;
        uint32_t nx = (cw < WPR - 1) ? mb[gw + 1]   : 0u;
        uint32_t lf = (m << 1) | (pv >> 31);
        uint32_t rt = (m >> 1) | (nx << 31);
        uint32_t e = m & ~(up & dn & lf & rt);
        buf[0][gw] = e;
        g_eb[slice * NWORDS + gw] = e;
        P0[j] = 0u; P1[j] = 0u; P2[j] = 0u; P3[j] = 0u; P4[j] = 0u;
    }
    __syncthreads();

    // cascaded 3x3 OR-dilations with saturation early-exit
    int extra = 0;
    int sb = 0;
    for (int r = 1; r <= 20; r++) {
        const uint32_t* src = buf[sb];
        uint32_t* dst = buf[sb ^ 1];
        uint32_t va[4];
#pragma unroll
        for (int k = 0; k < 4; k++) {
            int cw = cw0 + k - 1;
            uint32_t v = 0u;
            if (cw >= 0 && cw < WPR) {
                int gw = row * WPR + cw;
                v = src[gw];
                if (row)          v |= src[gw - WPR];
                if (row < HH - 1) v |= src[gw + WPR];
            }
            va[k] = v;
        }
        uint32_t allw = 0xffffffffu;
#pragma unroll
        for (int j = 0; j < 2; j++) {
            uint32_t c = va[j + 1];
            uint32_t nw = c | (c << 1) | (va[j] >> 31) | (c >> 1) | (va[j + 2] << 31);
            dst[wb + j] = nw;
            allw &= nw;
            uint32_t cy = nw, t;                    // ripple-carry +1 where covered
            t = P0[j] & cy; P0[j] ^= cy; cy = t;
            t = P1[j] & cy; P1[j] ^= cy; cy = t;
            t = P2[j] & cy; P2[j] ^= cy; cy = t;
            t = P3[j] & cy; P3[j] ^= cy; cy = t;
            P4[j] ^= cy;
        }
        sb ^= 1;
        if (__syncthreads_and(allw == 0xffffffffu)) { extra = 20 - r; break; }
    }
    if (tid == 0) g_extra[slice] = extra;

    // per-word metadata: acc = K + edge, K in {kt-1, kt} per word (typical)
#pragma unroll
    for (int j = 0; j < 2; j++) {
        int gw = wb + j;
        uint32_t p0 = P0[j], p1 = P1[j], p2 = P2[j], p3 = P3[j], p4 = P4[j];
        unsigned kt = ((p0 >> 31) & 1u) | (((p1 >> 31) & 1u) << 1)
                    | (((p2 >> 31) & 1u) << 2) | (((p3 >> 31) & 1u) << 3)
                    | (((p4 >> 31) & 1u) << 4);
        uint32_t mhi = ((kt & 1u)  ? p0 : ~p0) & ((kt & 2u)  ? p1 : ~p1)
                     & ((kt & 4u)  ? p2 : ~p2) & ((kt & 8u)  ? p3 : ~p3)
                     & ((kt & 16u) ? p4 : ~p4);
        uint32_t mlo = 0u;
        if (kt) {
            unsigned kl = kt - 1u;
            mlo = ((kl & 1u)  ? p0 : ~p0) & ((kl & 2u)  ? p1 : ~p1)
                & ((kl & 4u)  ? p2 : ~p2) & ((kl & 8u)  ? p3 : ~p3)
                & ((kl & 16u) ? p4 : ~p4);
        }
        bool valid = (mhi | mlo) == 0xffffffffu;
        int gi = slice * NWORDS + gw;
        g_bs[gi] = valid ? ((int)kt - 1 + extra) : -100;
        g_hm[gi] = mhi;
        if (!valid) {                               // rare: spill planes
            g_pl[0][gi] = p0;
            g_pl[1][gi] = p1;
            g_pl[2][gi] = p2;
            g_pl[3][gi] = p3;
            g_pl[4][gi] = p4;
        }
    }
}

// ================= K3: decode + weighted sums + finalize ======================
__global__ __launch_bounds__(256)
void decode_kernel(const float* __restrict__ outp, float* __restrict__ out) {
    __shared__ float lut[64];
    __shared__ double r0s[8], r1s[8], r2s[8];
    __shared__ int s_last;

    const int cta = blockIdx.x;
    const int slice = cta >> 3;                     // 8 CTAs per slice
    const int tid = threadIdx.x;
    const int lane = tid & 31;
    const int wid = tid >> 5;

    if (tid < 64) {
        int a = tid < 22 ? tid : 21;
        float dist = (22.0f - (float)a) / 22.0f;
        lut[tid] = 2.0f / (1.0f + expf(10.0f * dist));
    }
    __syncthreads();

    const float4* op4 = reinterpret_cast<const float4*>(outp);
    const size_t gb = (size_t)cta * 2048;           // float4 groups per CTA
    const int extra = g_extra[slice];

    // front-batch: 8 data LDG.128 + 8x4 metadata loads (metadata is L2-hot)
    float4 va[8];
    uint32_t mbv[8], ebv[8], hmv[8];
    int bsv[8];
#pragma unroll
    for (int j = 0; j < 8; j++)
        va[j] = op4[gb + (size_t)j * 256 + tid];
#pragma unroll
    for (int j = 0; j < 8; j++) {
        size_t w = (gb + (size_t)j * 256 + tid) >> 3;
        mbv[j] = g_mb[w];
        ebv[j] = g_eb[w];
        hmv[j] = g_hm[w];
        bsv[j] = g_bs[w];
    }

    float s_ia = 0.f, s_in = 0.f, s_ta = 0.f;
#pragma unroll
    for (int j = 0; j < 8; j++) {
        size_t g = gb + (size_t)j * 256 + tid;
        int i0 = ((int)g & 7) * 4;
        uint32_t qm = mbv[j] >> i0;
        uint32_t qe = ebv[j] >> i0;
        float vv[4] = {va[j].x, va[j].y, va[j].z, va[j].w};
        if (bsv[j] != -100) {
            uint32_t qh = hmv[j] >> i0;
#pragma unroll
            for (int e = 0; e < 4; e++) {
                int idx = bsv[j] + (int)((qh >> e) & 1u) + (int)((qe >> e) & 1u);
                float w = lut[idx];
                float f = vv[e] * w;
                s_ia += f;
                if ((qm >> e) & 1u) { s_in += f; s_ta += w; }
            }
        } else {
            size_t wdx = g >> 3;
            uint32_t q0 = g_pl[0][wdx] >> i0;
            uint32_t q1 = g_pl[1][wdx] >> i0;
            uint32_t q2 = g_pl[2][wdx] >> i0;
            uint32_t q3 = g_pl[3][wdx] >> i0;
            uint32_t q4 = g_pl[4][wdx] >> i0;
#pragma unroll
            for (int e = 0; e < 4; e++) {
                unsigned a = ((q0 >> e) & 1u)
                           | (((q1 >> e) & 1u) << 1)
                           | (((q2 >> e) & 1u) << 2)
                           | (((q3 >> e) & 1u) << 3)
                           | (((q4 >> e) & 1u) << 4);
                a += ((qe >> e) & 1u) + extra;
                float w = lut[a];
                float f = vv[e] * w;
                s_ia += f;
                if ((qm >> e) & 1u) { s_in += f; s_ta += w; }
            }
        }
    }

    // CTA reduce -> g_cta[cta]
    double d0 = (double)s_in, d1 = (double)s_ia, d2 = (double)s_ta;
#pragma unroll
    for (int o = 16; o > 0; o >>= 1) {
        d0 += __shfl_down_sync(0xffffffffu, d0, o);
        d1 += __shfl_down_sync(0xffffffffu, d1, o);
        d2 += __shfl_down_sync(0xffffffffu, d2, o);
    }
    if (lane == 0) { r0s[wid] = d0; r1s[wid] = d1; r2s[wid] = d2; }
    __syncthreads();
    if (wid == 0) {
        double a0 = (lane < 8) ? r0s[lane] : 0.0;
        double a1 = (lane < 8) ? r1s[lane] : 0.0;
        double a2 = (lane < 8) ? r2s[lane] : 0.0;
#pragma unroll
        for (int o = 4; o > 0; o >>= 1) {
            a0 += __shfl_down_sync(0xffffffffu, a0, o);
            a1 += __shfl_down_sync(0xffffffffu, a1, o);
            a2 += __shfl_down_sync(0xffffffffu, a2, o);
        }
        if (lane == 0) {
            g_cta[cta][0] = a0;
            g_cta[cta][1] = a1;
            g_cta[cta][2] = a2;
        }
    }

    // last-arriving CTA finalizes the scalar loss
    if (tid == 0) {
        __threadfence();
        unsigned t = atomicAdd(&g_ticket, 1u);
        s_last = (t == NCTA - 1);
    }
    __syncthreads();
    if (s_last) {
        __threadfence();
        __shared__ double fin[3][8];
        double loss = 0.0;
        for (int b = 0; b < BATCH; b++) {
            int j0 = b * 512 + tid;                 // batch b owns CTAs [b*512, b*512+512)
            double i0 = g_cta[j0][0] + g_cta[j0 + 256][0];
            double a0 = g_cta[j0][1] + g_cta[j0 + 256][1];
            double t0 = g_cta[j0][2] + g_cta[j0 + 256][2];
#pragma unroll
            for (int o = 16; o > 0; o >>= 1) {
                i0 += __shfl_down_sync(0xffffffffu, i0, o);
                a0 += __shfl_down_sync(0xffffffffu, a0, o);
                t0 += __shfl_down_sync(0xffffffffu, t0, o);
            }
            if (lane == 0) { fin[0][wid] = i0; fin[1][wid] = a0; fin[2][wid] = t0; }
            __syncthreads();
            if (tid == 0) {
                double I = 0.0, A = 0.0, T = 0.0;
#pragma unroll
                for (int q = 0; q < 8; q++) { I += fin[0][q]; A += fin[1][q]; T += fin[2][q]; }
                loss += (T == 0.0) ? 0.0 : (1.0 - 2.0 * I / (A + T + 2.0e-6));
            }
            __syncthreads();
        }
        if (tid == 0) {
            out[0] = (float)(loss * 0.5);           // mean over BATCH=2
            g_ticket = 0;                           // reset for next graph replay
        }
    }
}

extern "C" void kernel_launch(void* const* d_in, const int* in_sizes, int n_in,
                              void* d_out, int out_size) {
    const float* outputs = (const float*)d_in[0];  // float32 [2,1,64,256,256]
    const int*   masks   = (const int*)d_in[1];    // int32   [2,1,64,256,256]
    float* out = (float*)d_out;

    pack_kernel<<<NCTA, 256>>>(masks);
    cascade_kernel<<<SLICES, 1024>>>();
    decode_kernel<<<NCTA, 256>>>(outputs, out);
}